// round 8
// baseline (speedup 1.0000x reference)
#include <cuda_runtime.h>
#include <cuda_bf16.h>

// IDWT 2D (inverse Haar), reference-exact layout.
// Input x: (B=8, 4*C=256, H=128, W=128) fp32 -> Output (8, 64, 256, 256) fp32.
//
// Mapping from the reference's raw (H,W,2,2)->(2H,2W) reshape:
//   input (i,j) -> float4 at row = 2i + (j>=64), col = 4*(j mod 64)
//   butterfly = (ll+lh+hl+hh, ll+lh-hl-hh, ll-lh+hl-hh, ll-lh-hl+hh)
//
// Each thread handles TWO j-pairs: (j=2jv, 2jv+1) and (j=2jv+64, 2jv+65),
// jv in [0,32). Both land at the same output columns, rows 2i and 2i+1.
//   loads : 8x LDG.64, all independent, batched at the front (64B in flight
//           per thread at the proven-best 8B access width)
//   stores: 4x STG.128; each warp covers a full 1KB row segment per 2 instrs.

static constexpr int B  = 8;
static constexpr int C  = 64;
static constexpr int H  = 128;
static constexpr int W  = 128;
static constexpr int JT = 32;    // j-pair index within first half-row

static constexpr unsigned BAND_STRIDE = (unsigned)C * H * W;      // 1,048,576
static constexpr unsigned X_N_STRIDE  = 4u * BAND_STRIDE;
static constexpr unsigned O_C_STRIDE  = 2u * H * 2u * W;          // 65,536
static constexpr unsigned O_N_STRIDE  = (unsigned)C * O_C_STRIDE;

__device__ __forceinline__ float4 butterfly2(float2 ll, float2 lh, float2 hl, float2 hh,
                                             int elem /*0 or 1*/)
{
    float a = elem ? ll.y : ll.x;
    float b = elem ? lh.y : lh.x;
    float g = elem ? hl.y : hl.x;
    float h = elem ? hh.y : hh.x;
    float s = a + b, d = a - b;
    float sb = g + h, db = g - h;
    float4 q;
    q.x = s + sb;
    q.y = s - sb;
    q.z = d + db;
    q.w = d - db;
    return q;
}

__global__ void __launch_bounds__(256) idwt2d_kernel(const float* __restrict__ x,
                                                     float* __restrict__ out)
{
    unsigned tid = blockIdx.x * blockDim.x + threadIdx.x;  // 2,097,152 threads

    unsigned jv = tid & (JT - 1);        // 0..31
    unsigned t1 = tid >> 5;
    unsigned i  = t1 & (H - 1);          // 0..127
    unsigned t2 = t1 >> 7;
    unsigned c  = t2 & (C - 1);          // 0..63
    unsigned n  = t2 >> 6;               // 0..7

    unsigned xbase = n * X_N_STRIDE + c * (H * W) + i * W + 2 * jv;

    // First half-row pair (j = 2jv, 2jv+1) and second half (j = 2jv+64, +65):
    // 8 independent 8B loads, batched.
    const float* p = x + xbase;
    float2 ll0 = *(const float2*)(p + 0 * BAND_STRIDE);
    float2 lh0 = *(const float2*)(p + 1 * BAND_STRIDE);
    float2 hl0 = *(const float2*)(p + 2 * BAND_STRIDE);
    float2 hh0 = *(const float2*)(p + 3 * BAND_STRIDE);
    float2 ll1 = *(const float2*)(p + 0 * BAND_STRIDE + 64);
    float2 lh1 = *(const float2*)(p + 1 * BAND_STRIDE + 64);
    float2 hl1 = *(const float2*)(p + 2 * BAND_STRIDE + 64);
    float2 hh1 = *(const float2*)(p + 3 * BAND_STRIDE + 64);

    float4 q00 = butterfly2(ll0, lh0, hl0, hh0, 0);  // j=2jv    -> row 2i,   col 8jv
    float4 q01 = butterfly2(ll0, lh0, hl0, hh0, 1);  // j=2jv+1  -> row 2i,   col 8jv+4
    float4 q10 = butterfly2(ll1, lh1, hl1, hh1, 0);  // j=2jv+64 -> row 2i+1, col 8jv
    float4 q11 = butterfly2(ll1, lh1, hl1, hh1, 1);  // j=2jv+65 -> row 2i+1, col 8jv+4

    unsigned col   = 8 * jv;
    unsigned obase = n * O_N_STRIDE + c * O_C_STRIDE + (2 * i) * (2 * W) + col;

    float4* o0 = (float4*)(out + obase);             // row 2i
    float4* o1 = (float4*)(out + obase + 2 * W);     // row 2i+1
    o0[0] = q00;
    o0[1] = q01;
    o1[0] = q10;
    o1[1] = q11;
}

extern "C" void kernel_launch(void* const* d_in, const int* in_sizes, int n_in,
                              void* d_out, int out_size)
{
    const float* x = (const float*)d_in[0];
    float* out = (float*)d_out;

    const unsigned total = (unsigned)B * C * H * JT;  // 2,097,152
    const int threads = 256;
    const int blocks = total / threads;               // 8192

    idwt2d_kernel<<<blocks, threads>>>(x, out);
}